// round 5
// baseline (speedup 1.0000x reference)
#include <cuda_runtime.h>
#include <cuda_bf16.h>
#include <stdint.h>

// Problem dims (fixed by the dataset)
#define NBATCH 4
#define NROWS  8192
#define DMEM   128
#define NTILES 64
#define PADB   272          // padded row stride (bytes): 68 words -> conflict-free ldmatrix
#define TILEP  (128 * PADB) // 34816 B per 128x128 bf16 tile
#define THRESH 0.65f
#define NSTRIP 128          // 4 batches * 32 pair-strips
#define STRIPT 65           // tiles per strip (row p: 64-p, row 63-p: p+1)
#define TOTTIL (NSTRIP * STRIPT)  // 8320
#define NCTA   296          // 2 per SM * 148 SMs -> one balanced wave

// Scratch (device globals are the sanctioned scratch mechanism)
__device__ __align__(16) __nv_bfloat16 g_proj[(size_t)NBATCH * NROWS * DMEM]; // 8 MB normalized proj
__device__ __align__(16) __nv_bfloat16 g_wb[DMEM * DMEM];                     // 32 KB bf16 W
__device__ float g_deg[NBATCH * NROWS];

// ---------------------------------------------------------------------------
// helpers
// ---------------------------------------------------------------------------
__device__ __forceinline__ uint32_t su32(const void* p) {
    uint32_t a;
    asm("{ .reg .u64 t; cvta.to.shared.u64 t, %1; cvt.u32.u64 %0, t; }" : "=r"(a) : "l"(p));
    return a;
}

#define LDMATRIX_X4(r0, r1, r2, r3, addr) \
    asm volatile("ldmatrix.sync.aligned.m8n8.x4.shared.b16 {%0,%1,%2,%3}, [%4];" \
                 : "=r"(r0), "=r"(r1), "=r"(r2), "=r"(r3) : "r"(addr))

#define MMA_BF16(d, a, b0, b1) \
    asm volatile("mma.sync.aligned.m16n8k16.row.col.f32.bf16.bf16.f32 " \
                 "{%0,%1,%2,%3}, {%4,%5,%6,%7}, {%8,%9}, {%0,%1,%2,%3};" \
                 : "+f"((d)[0]), "+f"((d)[1]), "+f"((d)[2]), "+f"((d)[3]) \
                 : "r"((a)[0]), "r"((a)[1]), "r"((a)[2]), "r"((a)[3]), "r"(b0), "r"(b1))

// bf16 128x128 tile gmem(row-major) -> smem(272B padded rows). 256 threads.
__device__ __forceinline__ void copy_tileP(uint32_t dst, const __nv_bfloat16* src, int tid) {
    #pragma unroll
    for (int k = 0; k < 8; k++) {
        int idx = tid + k * 256;             // 2048 16B chunks
        int r = idx >> 4, c = idx & 15;
        asm volatile("cp.async.cg.shared.global [%0], [%1], 16;"
                     :: "r"(dst + (uint32_t)(r * PADB + c * 16)),
                        "l"((const char*)src + (size_t)idx * 16) : "memory");
    }
}

// This warp's resident A fragments (m32 x k128) from padded smA.
__device__ __forceinline__ void load_afrags(uint32_t a[2][8][4], uint32_t smA, int wm, int l) {
    #pragma unroll
    for (int m = 0; m < 2; m++) {
        uint32_t base = smA + (uint32_t)((wm * 32 + m * 16 + (l & 15)) * PADB + ((l >> 4) & 1) * 16);
        #pragma unroll
        for (int k = 0; k < 8; k++)
            LDMATRIX_X4(a[m][k][0], a[m][k][1], a[m][k][2], a[m][k][3], base + k * 32);
    }
}

// Decode global tile id -> (batch, it, jt). Strip s covers row p then row 63-p.
__device__ __forceinline__ void dec_tile(int g, int& b, int& it, int& jt) {
    int s = g / STRIPT, t = g - s * STRIPT;
    int p = s & 31, n0 = 64 - p;
    b = s >> 5;
    if (t < n0) { it = p;      jt = p + t; }
    else        { it = 63 - p; jt = (63 - p) + (t - n0); }
}

// ---------------------------------------------------------------------------
// Stage 0: out = X (analytic diagonal term); W -> bf16; zero g_deg
// ---------------------------------------------------------------------------
__global__ void __launch_bounds__(256) prep_kernel(const float* __restrict__ X,
                                                   const float* __restrict__ W,
                                                   float* __restrict__ out) {
    int b = blockIdx.x, tid = threadIdx.x;
    if (b < 2048) {                                    // out = X
        size_t g = ((size_t)b * 256 + tid) * 2;
        reinterpret_cast<float4*>(out)[g]     = reinterpret_cast<const float4*>(X)[g];
        reinterpret_cast<float4*>(out)[g + 1] = reinterpret_cast<const float4*>(X)[g + 1];
    } else if (b < 2056) {                             // W -> bf16
        size_t g = ((size_t)(b - 2048) * 256 + tid) * 2;
        float4 a0 = reinterpret_cast<const float4*>(W)[g];
        float4 a1 = reinterpret_cast<const float4*>(W)[g + 1];
        __nv_bfloat162 h0 = __floats2bfloat162_rn(a0.x, a0.y);
        __nv_bfloat162 h1 = __floats2bfloat162_rn(a0.z, a0.w);
        __nv_bfloat162 h2 = __floats2bfloat162_rn(a1.x, a1.y);
        __nv_bfloat162 h3 = __floats2bfloat162_rn(a1.z, a1.w);
        reinterpret_cast<uint4*>(g_wb)[g / 2] =
            make_uint4(*(uint32_t*)&h0, *(uint32_t*)&h1, *(uint32_t*)&h2, *(uint32_t*)&h3);
    } else {                                           // zero g_deg
        size_t g = ((size_t)(b - 2056) * 256 + tid) * 2;
        reinterpret_cast<float4*>(g_deg)[g]     = make_float4(0.f, 0.f, 0.f, 0.f);
        reinterpret_cast<float4*>(g_deg)[g + 1] = make_float4(0.f, 0.f, 0.f, 0.f);
    }
}

// ---------------------------------------------------------------------------
// Stage 1: proj = normalize(X @ W^T + b) -> bf16 row-major, via bf16 mma.
// X read as fp32 and converted to bf16 on the way into padded smem.
// CTA: 256 thr, 8 warps; warp w owns rows w*16..+15, full n=128.
// ---------------------------------------------------------------------------
__global__ void __launch_bounds__(256) proj_kernel(const float* __restrict__ X,
                                                   const float* __restrict__ Bv) {
    extern __shared__ unsigned char dsm[];
    uint32_t smX = su32(dsm);                 // TILEP
    uint32_t smW = smX + TILEP;               // TILEP
    float* bs = (float*)(dsm + 2 * TILEP);    // 512 B

    int tid = threadIdx.x, w = tid >> 5, l = tid & 31;
    int r0 = blockIdx.x * 128;

    copy_tileP(smW, g_wb, tid);
    asm volatile("cp.async.commit_group;" ::: "memory");
    if (tid < 128) bs[tid] = Bv[tid];

    // X fp32 -> bf16 into padded smem (each thread: 8 chunks of 8 floats)
    #pragma unroll
    for (int k = 0; k < 8; k++) {
        int idx = tid + k * 256;
        int r = idx >> 4, c = idx & 15;
        size_t gbase = ((size_t)(r0 + r) * DMEM + c * 8);
        float4 f0 = reinterpret_cast<const float4*>(X + gbase)[0];
        float4 f1 = reinterpret_cast<const float4*>(X + gbase)[1];
        __nv_bfloat162 h0 = __floats2bfloat162_rn(f0.x, f0.y);
        __nv_bfloat162 h1 = __floats2bfloat162_rn(f0.z, f0.w);
        __nv_bfloat162 h2 = __floats2bfloat162_rn(f1.x, f1.y);
        __nv_bfloat162 h3 = __floats2bfloat162_rn(f1.z, f1.w);
        *reinterpret_cast<uint4*>(dsm + r * PADB + c * 16) =
            make_uint4(*(uint32_t*)&h0, *(uint32_t*)&h1, *(uint32_t*)&h2, *(uint32_t*)&h3);
    }
    asm volatile("cp.async.wait_group 0;" ::: "memory");
    __syncthreads();

    float acc[16][4];
    #pragma unroll
    for (int f = 0; f < 16; f++)
        #pragma unroll
        for (int p = 0; p < 4; p++) acc[f][p] = 0.f;

    #pragma unroll
    for (int k = 0; k < 8; k++) {
        uint32_t a[4];
        {
            uint32_t addr = smX + (uint32_t)((w * 16 + (l & 15)) * PADB + ((l >> 4) & 1) * 16 + k * 32);
            LDMATRIX_X4(a[0], a[1], a[2], a[3], addr);
        }
        #pragma unroll
        for (int nf = 0; nf < 8; nf++) {
            uint32_t addr = smW + (uint32_t)((nf * 16 + (l & 7) + ((l & 16) ? 8 : 0)) * PADB
                                             + ((l >> 3) & 1) * 16 + k * 32);
            uint32_t b0, b1, b2, b3;
            LDMATRIX_X4(b0, b1, b2, b3, addr);
            MMA_BF16(acc[nf * 2],     a, b0, b1);
            MMA_BF16(acc[nf * 2 + 1], a, b2, b3);
        }
    }

    // bias + row sums of squares (rows l/4 and l/4+8 of this warp's m16)
    float slo = 0.f, shi = 0.f;
    #pragma unroll
    for (int f = 0; f < 16; f++) {
        int c0 = f * 8 + 2 * (l & 3);
        float b0 = bs[c0], b1 = bs[c0 + 1];
        acc[f][0] += b0; acc[f][1] += b1;
        acc[f][2] += b0; acc[f][3] += b1;
        slo += acc[f][0] * acc[f][0] + acc[f][1] * acc[f][1];
        shi += acc[f][2] * acc[f][2] + acc[f][3] * acc[f][3];
    }
    slo += __shfl_xor_sync(0xffffffffu, slo, 1);
    slo += __shfl_xor_sync(0xffffffffu, slo, 2);
    shi += __shfl_xor_sync(0xffffffffu, shi, 1);
    shi += __shfl_xor_sync(0xffffffffu, shi, 2);
    float rlo = rsqrtf(fmaxf(slo, 1e-24f));
    float rhi = rsqrtf(fmaxf(shi, 1e-24f));

    int rowlo = r0 + w * 16 + (l >> 2);
    #pragma unroll
    for (int f = 0; f < 16; f++) {
        int c0 = f * 8 + 2 * (l & 3);
        __nv_bfloat162 hlo = __floats2bfloat162_rn(acc[f][0] * rlo, acc[f][1] * rlo);
        __nv_bfloat162 hhi = __floats2bfloat162_rn(acc[f][2] * rhi, acc[f][3] * rhi);
        *reinterpret_cast<uint32_t*>(g_proj + (size_t)rowlo * DMEM + c0)       = *(uint32_t*)&hlo;
        *reinterpret_cast<uint32_t*>(g_proj + (size_t)(rowlo + 8) * DMEM + c0) = *(uint32_t*)&hhi;
    }
}

// ---------------------------------------------------------------------------
// Stage 2: upper-triangular sim tiles via bf16 mma.sync.
// 296 persistent CTAs, each a contiguous slice of the 8320-tile list
// (strip-major for A reuse). Symmetric hit updates; diagonal analytic.
// ---------------------------------------------------------------------------
__global__ void __launch_bounds__(256, 2) sim_kernel(const float* __restrict__ X,
                                                     float* __restrict__ out) {
    extern __shared__ unsigned char dsm[];
    uint32_t smA  = su32(dsm);
    uint32_t smB0 = smA + TILEP;
    uint32_t smB1 = smA + 2 * TILEP;

    int tid = threadIdx.x, wid = tid >> 5, l = tid & 31;
    int wm = wid >> 1, wn = wid & 1;

    int c = blockIdx.x;
    int g0 = (int)(((long long)c * TOTTIL) / NCTA);
    int g1 = (int)(((long long)(c + 1) * TOTTIL) / NCTA);

    #define PROJT(b, t) (g_proj + ((size_t)(b) * NROWS + (size_t)(t) * 128) * DMEM)

    int b, it, jt;
    dec_tile(g0, b, it, jt);
    int cur_b = b, cur_it = it;

    copy_tileP(smA, PROJT(b, it), tid);
    copy_tileP(smB0, PROJT(b, jt), tid);
    asm volatile("cp.async.commit_group;" ::: "memory");
    if (g0 + 1 < g1) {
        int b2, i2, j2; dec_tile(g0 + 1, b2, i2, j2);
        copy_tileP(smB1, PROJT(b2, j2), tid);
    }
    asm volatile("cp.async.commit_group;" ::: "memory");
    asm volatile("cp.async.wait_group 1;" ::: "memory");
    __syncthreads();

    uint32_t a[2][8][4];
    load_afrags(a, smA, wm, l);

    for (int g = g0; g < g1; ++g) {
        dec_tile(g, b, it, jt);
        if (it != cur_it || b != cur_b) {            // row/batch crossing (rare)
            cur_it = it; cur_b = b;
            copy_tileP(smA, PROJT(b, it), tid);
            asm volatile("cp.async.commit_group;" ::: "memory");
            asm volatile("cp.async.wait_group 0;" ::: "memory");
            __syncthreads();
            load_afrags(a, smA, wm, l);
        }
        uint32_t smB = ((g - g0) & 1) ? smB1 : smB0;

        const float* Xb = X + (size_t)b * NROWS * DMEM;
        float* outb = out + (size_t)b * NROWS * DMEM;
        float* degb = g_deg + b * NROWS;

        #pragma unroll 1
        for (int grp = 0; grp < 4; grp++) {
            int n0c = wn * 64 + grp * 16;
            float d[2][2][4];
            #pragma unroll
            for (int m = 0; m < 2; m++)
                #pragma unroll
                for (int h = 0; h < 2; h++)
                    #pragma unroll
                    for (int pp = 0; pp < 4; pp++) d[m][h][pp] = 0.f;

            uint32_t bbase = smB + (uint32_t)((n0c + (l & 7) + ((l & 16) ? 8 : 0)) * PADB
                                              + ((l >> 3) & 1) * 16);
            #pragma unroll
            for (int k = 0; k < 8; k++) {
                uint32_t b0, b1, b2, b3;
                LDMATRIX_X4(b0, b1, b2, b3, bbase + k * 32);
                #pragma unroll
                for (int m = 0; m < 2; m++) {
                    MMA_BF16(d[m][0], a[m][k], b0, b1);
                    MMA_BF16(d[m][1], a[m][k], b2, b3);
                }
            }

            float vmax = d[0][0][0];
            #pragma unroll
            for (int m = 0; m < 2; m++)
                #pragma unroll
                for (int h = 0; h < 2; h++)
                    #pragma unroll
                    for (int pp = 0; pp < 4; pp++) vmax = fmaxf(vmax, d[m][h][pp]);
            unsigned warp_any = __ballot_sync(0xffffffffu, vmax > THRESH);

            if (warp_any) {   // rare: diagonal tile self-sims, or a true hit
                bool diag = (it == jt);
                #pragma unroll
                for (int m = 0; m < 2; m++)
                    #pragma unroll
                    for (int h = 0; h < 2; h++)
                        #pragma unroll
                        for (int pp = 0; pp < 4; pp++) {
                            unsigned msk = __ballot_sync(0xffffffffu, d[m][h][pp] > THRESH);
                            while (msk) {
                                int bb = __ffs(msk) - 1; msk &= msk - 1;
                                int ib = it * 128 + wm * 32 + m * 16 + (bb >> 2) + ((pp & 2) ? 8 : 0);
                                int jb = jt * 128 + n0c + h * 8 + ((bb & 3) << 1) + (pp & 1);
                                if (ib != jb) {
                                    float4 xj = reinterpret_cast<const float4*>(Xb + (size_t)jb * DMEM)[l];
                                    float* oi = outb + (size_t)ib * DMEM + l * 4;
                                    atomicAdd(oi + 0, xj.x); atomicAdd(oi + 1, xj.y);
                                    atomicAdd(oi + 2, xj.z); atomicAdd(oi + 3, xj.w);
                                    if (l == 0) atomicAdd(&degb[ib], 1.0f);
                                    if (!diag) {   // symmetric partner (jb, ib)
                                        float4 xi = reinterpret_cast<const float4*>(Xb + (size_t)ib * DMEM)[l];
                                        float* oj = outb + (size_t)jb * DMEM + l * 4;
                                        atomicAdd(oj + 0, xi.x); atomicAdd(oj + 1, xi.y);
                                        atomicAdd(oj + 2, xi.z); atomicAdd(oj + 3, xi.w);
                                        if (l == 0) atomicAdd(&degb[jb], 1.0f);
                                    }
                                }
                            }
                        }
            }
        }

        __syncthreads();                         // all warps done reading smB
        if (g + 2 < g1) {
            int b2, i2, j2; dec_tile(g + 2, b2, i2, j2);
            copy_tileP(smB, PROJT(b2, j2), tid);
        }
        asm volatile("cp.async.commit_group;" ::: "memory");
        asm volatile("cp.async.wait_group 1;" ::: "memory");  // next B landed
        __syncthreads();
    }
    #undef PROJT
}

// ---------------------------------------------------------------------------
// Stage 3: out[i] *= 1/(1 + deg_hits[i])   (out already holds X[i] + hits)
// ---------------------------------------------------------------------------
__global__ void __launch_bounds__(256) fin_kernel(float* __restrict__ out) {
    size_t v = (size_t)blockIdx.x * 256 + threadIdx.x;
    int row = (int)(v >> 5);
    float inv = 1.0f / (1.0f + g_deg[row]);
    float4 o = reinterpret_cast<float4*>(out)[v];
    o.x *= inv; o.y *= inv; o.z *= inv; o.w *= inv;
    reinterpret_cast<float4*>(out)[v] = o;
}

// ---------------------------------------------------------------------------
extern "C" void kernel_launch(void* const* d_in, const int* in_sizes, int n_in,
                              void* d_out, int out_size) {
    (void)in_sizes; (void)n_in; (void)out_size;
    const float* X  = (const float*)d_in[0];
    const float* W  = (const float*)d_in[1];
    const float* Bv = (const float*)d_in[2];
    float* out = (float*)d_out;

    const int PROJ_SMEM = 2 * TILEP + 512;     // ~70 KB
    const int SIM_SMEM  = 3 * TILEP;           // ~102 KB (2 CTAs/SM)
    cudaFuncSetAttribute(proj_kernel, cudaFuncAttributeMaxDynamicSharedMemorySize, PROJ_SMEM);
    cudaFuncSetAttribute(sim_kernel,  cudaFuncAttributeMaxDynamicSharedMemorySize, SIM_SMEM);

    prep_kernel<<<2072, 256>>>(X, W, out);
    proj_kernel<<<(NBATCH * NROWS) / 128, 256, PROJ_SMEM>>>(X, Bv);
    sim_kernel<<<NCTA, 256, SIM_SMEM>>>(X, out);
    fin_kernel<<<(NBATCH * NROWS * DMEM / 4) / 256, 256>>>(out);
}